// round 1
// baseline (speedup 1.0000x reference)
#include <cuda_runtime.h>
#include <cuda_bf16.h>
#include <mma.h>

using namespace nvcuda;

#define B_   2
#define L_   2048
#define D_   128
#define H_   8
#define HD_  32
#define HB_  16            // H_*B_
// (1/sqrt(HD)) * log2(e): fold into Q so softmax exp is a single exp2f (MUFU.EX2)
#define QSCALE 0.2550348f
#define SLD  68            // padded leading dim for score smem tiles (mult of 4)

// ---- device scratch (static allocation only; no cudaMalloc allowed) ----
__device__ float         g_vv[HB_ * L_];       // vv[hb][j] = sigmoid(x[b, L-1-j] . Wv[:,h])
__device__ float         g_invZ[HB_ * L_];     // 1 / softmax row sum
__device__ float         g_S[HB_ * L_];        // diagonal sums
__device__ __nv_bfloat16 g_Q[HB_ * L_ * HD_];  // pre-scaled Q, bf16
__device__ __nv_bfloat16 g_K[HB_ * L_ * HD_];  // K, bf16

// ============================================================================
// Kernel 1: Q/K projection. xp = x + pe; q = (xp@Wq + bq)*QSCALE; k = xp@Wk + bk
// block = 256 threads (one per output column), 16 (b,l) rows per block.
// ============================================================================
__global__ void qk_kernel(const float* __restrict__ x, const float* __restrict__ pe,
                          const float* __restrict__ Wq, const float* __restrict__ bq,
                          const float* __restrict__ Wk, const float* __restrict__ bk) {
    __shared__ float xs[16][D_];
    int row0 = blockIdx.x * 16;
    for (int i = threadIdx.x; i < 16 * D_; i += 256) {
        int r = i >> 7, d = i & (D_ - 1);
        int row = row0 + r;
        int l = row & (L_ - 1);
        xs[r][d] = x[row * D_ + d] + pe[l * D_ + d];
    }
    __syncthreads();

    int c = threadIdx.x;  // 0..255 output column
    float accq[16], acck[16];
#pragma unroll
    for (int r = 0; r < 16; r++) { accq[r] = 0.f; acck[r] = 0.f; }

#pragma unroll 4
    for (int d = 0; d < D_; d++) {
        float wq = Wq[d * 256 + c];
        float wk = Wk[d * 256 + c];
#pragma unroll
        for (int r = 0; r < 16; r++) {
            float xv = xs[r][d];
            accq[r] = fmaf(xv, wq, accq[r]);
            acck[r] = fmaf(xv, wk, acck[r]);
        }
    }

    float bqv = bq[c], bkv = bk[c];
    int h = c >> 5, hd = c & 31;
#pragma unroll
    for (int r = 0; r < 16; r++) {
        int row = row0 + r;
        int b = row >> 11, l = row & (L_ - 1);
        size_t off = ((size_t)(h * B_ + b) * L_ + l) * HD_ + hd;
        g_Q[off] = __float2bfloat16((accq[r] + bqv) * QSCALE);
        g_K[off] = __float2bfloat16(acck[r] + bkv);
    }
}

// ============================================================================
// Kernel 2: v = sigmoid(x @ Wv), stored reversed along j:  vv[hb][j] = v[b,L-1-j,h]
// ============================================================================
__global__ void v_kernel(const float* __restrict__ x, const float* __restrict__ Wv) {
    int t = blockIdx.x * 256 + threadIdx.x;  // 32768 threads
    int h = t & 7, row = t >> 3;             // row = b*L + l
    const float* xr = x + (size_t)row * D_;
    float acc = 0.f;
#pragma unroll 8
    for (int d = 0; d < D_; d++) acc = fmaf(xr[d], Wv[d * H_ + h], acc);
    float s = 1.f / (1.f + __expf(-acc));
    int b = row >> 11, l = row & (L_ - 1);
    g_vv[(h * B_ + b) * L_ + (L_ - 1 - l)] = s;
}

// ============================================================================
// Kernel 3 (pass 1): softmax row sums Z (no max subtraction — scores bounded).
// Block: 128 thr (4 warps), 64 q-rows, loops over all 2048 k in tiles of 64.
// Each warp computes a 16x64 score tile with wmma bf16 and accumulates exp2.
// Also zeroes g_S for the following pass.
// ============================================================================
__global__ void z_kernel() {
    __shared__ __nv_bfloat16 Qs[64 * HD_];
    __shared__ __nv_bfloat16 Ks[64 * HD_];
    __shared__ float Ss[4][16 * SLD];

    int hb = blockIdx.y;
    int q0 = blockIdx.x * 64;
    int tid = threadIdx.x, w = tid >> 5, lane = tid & 31;

    // zero g_S (512 blocks x 128 threads cover 32768 entries)
    int gt = (blockIdx.y * gridDim.x + blockIdx.x) * 128 + tid;
    if (gt < HB_ * L_) g_S[gt] = 0.f;

    // load Q tile (64x32 bf16 = 256 uint4)
    {
        const uint4* qsrc = (const uint4*)(g_Q + ((size_t)hb * L_ + q0) * HD_);
        uint4* qdst = (uint4*)Qs;
        for (int i = tid; i < 256; i += 128) qdst[i] = qsrc[i];
    }
    __syncthreads();

    wmma::fragment<wmma::matrix_a, 16, 16, 16, __nv_bfloat16, wmma::row_major> a0, a1;
    wmma::load_matrix_sync(a0, Qs + w * 16 * HD_, HD_);
    wmma::load_matrix_sync(a1, Qs + w * 16 * HD_ + 16, HD_);

    float zacc = 0.f;
    int r = lane >> 1, c0 = (lane & 1) * 32;  // lane -> (row, column half)

    for (int kt = 0; kt < L_ / 64; kt++) {
        __syncthreads();  // protect Ks and per-warp Ss reuse
        {
            const uint4* ksrc = (const uint4*)(g_K + ((size_t)hb * L_ + kt * 64) * HD_);
            uint4* kdst = (uint4*)Ks;
            for (int i = tid; i < 256; i += 128) kdst[i] = ksrc[i];
        }
        __syncthreads();

#pragma unroll
        for (int n = 0; n < 4; n++) {
            wmma::fragment<wmma::matrix_b, 16, 16, 16, __nv_bfloat16, wmma::col_major> b0, b1;
            wmma::load_matrix_sync(b0, Ks + n * 16 * HD_, HD_);
            wmma::load_matrix_sync(b1, Ks + n * 16 * HD_ + 16, HD_);
            wmma::fragment<wmma::accumulator, 16, 16, 16, float> cf;
            wmma::fill_fragment(cf, 0.f);
            wmma::mma_sync(cf, a0, b0, cf);
            wmma::mma_sync(cf, a1, b1, cf);
            wmma::store_matrix_sync(&Ss[w][n * 16], cf, SLD, wmma::mem_row_major);
        }
        __syncwarp();

        const float* srow = &Ss[w][r * SLD + c0];
#pragma unroll
        for (int j = 0; j < 32; j++) zacc += exp2f(srow[j]);
    }

    zacc += __shfl_xor_sync(0xffffffffu, zacc, 1);  // combine the two column halves
    if ((lane & 1) == 0)
        g_invZ[hb * L_ + q0 + w * 16 + r] = 1.f / zacc;
}

// ============================================================================
// Kernel 4 (pass 2): accumulate S[m] = sum over diagonal k-q=m of p * vv[k].
// Upper-triangle tiles only (kt >= blockIdx.x). Per-warp smem S buffers,
// lane-per-diagonal accumulation (no atomics in the hot loop).
// Dynamic smem: Qs|Ks|invZs|vvs|Ss|Sw = 58880 bytes.
// ============================================================================
__global__ void s_kernel() {
    extern __shared__ char smem[];
    __nv_bfloat16* Qs = (__nv_bfloat16*)smem;            // 4096 B
    __nv_bfloat16* Ks = (__nv_bfloat16*)(smem + 4096);   // 4096 B
    float* invZs = (float*)(smem + 8192);                // 256 B
    float* vvs   = (float*)(smem + 8448);                // 256 B
    float* Ssb   = (float*)(smem + 8704);                // 4*16*SLD*4 = 17408 B
    float* Sw    = (float*)(smem + 8704 + 4 * 16 * SLD * 4); // 4*2048*4 = 32768 B

    int hb = blockIdx.y, q0 = blockIdx.x * 64;
    int tid = threadIdx.x, w = tid >> 5, lane = tid & 31;
    float* Ssw = Ssb + w * 16 * SLD;
    float* Sww = Sw + w * L_;

    for (int i = tid; i < 4 * L_; i += 128) Sw[i] = 0.f;

    {
        const uint4* qsrc = (const uint4*)(g_Q + ((size_t)hb * L_ + q0) * HD_);
        uint4* qdst = (uint4*)Qs;
        for (int i = tid; i < 256; i += 128) qdst[i] = qsrc[i];
    }
    if (tid < 64) invZs[tid] = g_invZ[hb * L_ + q0 + tid];
    __syncthreads();

    wmma::fragment<wmma::matrix_a, 16, 16, 16, __nv_bfloat16, wmma::row_major> a0, a1;
    wmma::load_matrix_sync(a0, Qs + w * 16 * HD_, HD_);
    wmma::load_matrix_sync(a1, Qs + w * 16 * HD_ + 16, HD_);

    int q0w = q0 + w * 16;

    for (int kt = blockIdx.x; kt < L_ / 64; kt++) {  // skip tiles fully below diagonal
        int k0 = kt * 64;
        __syncthreads();
        {
            const uint4* ksrc = (const uint4*)(g_K + ((size_t)hb * L_ + k0) * HD_);
            uint4* kdst = (uint4*)Ks;
            for (int i = tid; i < 256; i += 128) kdst[i] = ksrc[i];
        }
        if (tid < 64) vvs[tid] = g_vv[hb * L_ + k0 + tid];
        __syncthreads();

#pragma unroll
        for (int n = 0; n < 4; n++) {
            wmma::fragment<wmma::matrix_b, 16, 16, 16, __nv_bfloat16, wmma::col_major> b0, b1;
            wmma::load_matrix_sync(b0, Ks + n * 16 * HD_, HD_);
            wmma::load_matrix_sync(b1, Ks + n * 16 * HD_ + 16, HD_);
            wmma::fragment<wmma::accumulator, 16, 16, 16, float> cf;
            wmma::fill_fragment(cf, 0.f);
            wmma::mma_sync(cf, a0, b0, cf);
            wmma::mma_sync(cf, a1, b1, cf);
            wmma::store_matrix_sync(&Ssw[n * 16], cf, SLD, wmma::mem_row_major);
        }
        __syncwarp();

        // diagonals of the 16x64 tile: dd = c - r in [-15, 63], m = k0 - q0w + dd
        int mbase = k0 - q0w;
        for (int t = lane; t < 79; t += 32) {
            int dd = t - 15;
            int m = mbase + dd;
            if (m >= 0) {
                int rlo = dd < 0 ? -dd : 0;
                int rhi = dd > 48 ? 63 - dd : 15;
                float sum = 0.f;
                for (int rr = rlo; rr <= rhi; rr++) {
                    float e = exp2f(Ssw[rr * SLD + rr + dd]);
                    sum = fmaf(e * invZs[w * 16 + rr], vvs[rr + dd], sum);
                }
                Sww[m] += sum;  // distinct m per lane, per-warp buffer: race-free
            }
        }
    }

    __syncthreads();
    int mlim = L_ - q0;  // m = k - q <= 2047 - q0 for this block
    for (int m = tid; m < mlim; m += 128) {
        float s = Sw[m] + Sw[L_ + m] + Sw[2 * L_ + m] + Sw[3 * L_ + m];
        atomicAdd(&g_S[hb * L_ + m], s);
    }
}

// ============================================================================
// Kernel 5: out[b,m,h] = (S[m-1]+S[m]+S[m+1]) / cnt(m),  cnt = 3 - edge corrections
// ============================================================================
__global__ void out_kernel(float* __restrict__ out) {
    int t = blockIdx.x * 256 + threadIdx.x;  // 32768
    int h = t & 7, m = (t >> 3) & (L_ - 1), b = t >> 14;
    const float* S = g_S + (h * B_ + b) * L_;
    float num = S[m];
    float cnt = 3.f;
    if (m > 0) num += S[m - 1]; else cnt = 2.f;
    if (m < L_ - 1) num += S[m + 1]; else cnt = 2.f;
    out[t] = num / cnt;
}

// ============================================================================
extern "C" void kernel_launch(void* const* d_in, const int* in_sizes, int n_in,
                              void* d_out, int out_size) {
    const float* x  = (const float*)d_in[0];
    const float* pe = (const float*)d_in[1];
    const float* Wq = (const float*)d_in[2];
    const float* bq = (const float*)d_in[3];
    const float* Wk = (const float*)d_in[4];
    const float* bk = (const float*)d_in[5];
    const float* Wv = (const float*)d_in[6];
    float* out = (float*)d_out;

    const int SMEM_S = 8704 + 4 * 16 * SLD * 4 + 4 * L_ * 4;  // 58880 B
    cudaFuncSetAttribute(s_kernel, cudaFuncAttributeMaxDynamicSharedMemorySize, SMEM_S);

    qk_kernel<<<256, 256>>>(x, pe, Wq, bq, Wk, bk);
    v_kernel<<<128, 256>>>(x, Wv);
    z_kernel<<<dim3(32, 16), 128>>>();
    s_kernel<<<dim3(32, 16), 128, SMEM_S>>>();
    out_kernel<<<128, 256>>>(out);
}